// round 3
// baseline (speedup 1.0000x reference)
#include <cuda_runtime.h>
#include <cuda_fp16.h>
#include <mma.h>
#include <cstdint>

using namespace nvcuda;

// Problem dims
#define B_  16
#define L_  512
#define Kn_ 48
#define E_  128
#define D_  384
#define H_  128

#define TILE_M  96
#define NTILES  4096          // (B*L*K)/TILE_M = 393216/96

// ---- smem layout (bytes) for k_main ----
// A1s   [96][392] half : 0       .. 75264
// Xs    [96][136] half : 75264   .. 101376
// W1s   [128][392]half : 101376  .. 201728
// C1s   [96][388] f32  : alias @75264  (after GEMM1; Xs/W1s dead)  end 224256
// CHK0  [64][392] half : alias @76800  (after A1s written; C1s dead)
// CHK1  [64][392] half : alias @126976
// C2s   [96][388] f32  : alias @76800  (after GEMM2; chunks dead)  end 225792
// idxs  [96] int       : 225792 .. 226176
#define OFF_A1S   0
#define OFF_XS    75264
#define OFF_W1S   101376
#define OFF_C1S   75264
#define OFF_CHK0  76800
#define OFF_CHK1  126976
#define OFF_C2S   76800
#define OFF_IDX   225792
#define SMEM_MAIN 226304

// head kernel smem
#define HOFF_HS   0            // [64][388] f32 = 99328
#define HOFF_H1   99328        // [64][132] f32 = 33792
#define HOFF_H2   133120       // [64][65]  f32 = 16640
#define SMEM_HEAD 149760

// ---- device scratch (no allocations allowed) ----
__device__ __align__(16) __half g_W1h[E_ * D_];
__device__ __align__(16) __half g_W2h[D_ * D_];
__device__ __align__(16) float  g_hbuf[(size_t)B_ * L_ * D_];
__device__ __align__(16) float  g_dG[B_ * L_];

__device__ __forceinline__ float geluf(float x) {
    return 0.5f * x * (1.0f + erff(x * 0.7071067811865476f));
}

__device__ __forceinline__ void cp_async16(void* dst, const void* src) {
    unsigned s = (unsigned)__cvta_generic_to_shared(dst);
    asm volatile("cp.async.cg.shared.global [%0], [%1], 16;\n" :: "r"(s), "l"(src) : "memory");
}
__device__ __forceinline__ void cp_commit() { asm volatile("cp.async.commit_group;\n" ::: "memory"); }
__device__ __forceinline__ void cp_wait0()  { asm volatile("cp.async.wait_group 0;\n" ::: "memory"); }

// ============================================================
// weight fp32 -> fp16 conversion (tiny)
// ============================================================
__global__ void k_convert(const float* __restrict__ fw1, const float* __restrict__ fw2) {
    int stride = gridDim.x * blockDim.x;
    int i0 = blockIdx.x * blockDim.x + threadIdx.x;
    for (int q = i0; q < E_ * D_; q += stride) g_W1h[q] = __float2half_rn(fw1[q]);
    for (int q = i0; q < D_ * D_; q += stride) g_W2h[q] = __float2half_rn(fw2[q]);
}

// ============================================================
// fused: GEMM1 + gelu + GEMM2 + gelu + gather(x_j) + K-reduce
// one CTA = 96 rows = 2 complete (b,l) groups -> writes 2 rows of h
// ============================================================
__global__ void __launch_bounds__(256, 1)
k_main(const float* __restrict__ h_V, const float* __restrict__ h_E,
       const float* __restrict__ fb1, const float* __restrict__ fb2,
       const int* __restrict__ E_idx)
{
    extern __shared__ unsigned char smem[];
    __half* A1s  = (__half*)(smem + OFF_A1S);    // [96][392]
    __half* Xs   = (__half*)(smem + OFF_XS);     // [96][136]
    __half* W1s  = (__half*)(smem + OFF_W1S);    // [128][392]
    float*  C1s  = (float*)(smem + OFF_C1S);     // [96][388]
    float*  C2s  = (float*)(smem + OFF_C2S);     // [96][388]
    __half* chk0 = (__half*)(smem + OFF_CHK0);   // [64][392]
    __half* chk1 = (__half*)(smem + OFF_CHK1);   // [64][392]
    int*    idxs = (int*)(smem + OFF_IDX);

    const int t = threadIdx.x;
    const int tile = blockIdx.x;
    const int rowbase = tile * TILE_M;
    const int b = rowbase / (L_ * Kn_);          // whole tile within one batch

    if (t < TILE_M) idxs[t] = E_idx[rowbase + t];

    // ---- stage W1 (fp16, cp.async) and X tile (fp32->fp16) ----
    for (int q = t; q < (E_ * D_) / 8; q += 256) {        // 6144 x 16B
        int r = q / 48, c8 = q - r * 48;
        cp_async16(W1s + r * 392 + c8 * 8, g_W1h + r * 384 + c8 * 8);
    }
    cp_commit();
    {
        const float4* Xg = reinterpret_cast<const float4*>(h_E + (size_t)rowbase * E_);
        for (int q = t; q < (TILE_M * E_) / 4; q += 256) {  // 3072 float4
            int m = q >> 5, c4 = q & 31;
            float4 v = Xg[q];
            __half2* d = reinterpret_cast<__half2*>(Xs + m * 136 + c4 * 4);
            d[0] = __floats2half2_rn(v.x, v.y);
            d[1] = __floats2half2_rn(v.z, v.w);
        }
    }
    cp_wait0();
    __syncthreads();

    // warp tiling: 8 warps in 2(m) x 4(n); warp tile = 48 x 96
    const int warp  = t >> 5;
    const int wm    = warp >> 2;     // 0..1
    const int wn    = warp & 3;      // 0..3
    const int mrow0 = wm * 48;
    const int ncol0 = wn * 96;

    wmma::fragment<wmma::accumulator, 16, 16, 16, float> acc[3][6];
#pragma unroll
    for (int i = 0; i < 3; i++)
#pragma unroll
        for (int j = 0; j < 6; j++) wmma::fill_fragment(acc[i][j], 0.0f);

    // ---- GEMM1: [96,128] @ [128,384] ----
#pragma unroll
    for (int k = 0; k < E_; k += 16) {
        wmma::fragment<wmma::matrix_a, 16, 16, 16, __half, wmma::row_major> af[3];
#pragma unroll
        for (int i = 0; i < 3; i++)
            wmma::load_matrix_sync(af[i], Xs + (mrow0 + i * 16) * 136 + k, 136);
#pragma unroll
        for (int j = 0; j < 6; j++) {
            wmma::fragment<wmma::matrix_b, 16, 16, 16, __half, wmma::row_major> bf;
            wmma::load_matrix_sync(bf, W1s + k * 392 + ncol0 + j * 16, 392);
#pragma unroll
            for (int i = 0; i < 3; i++) wmma::mma_sync(acc[i][j], af[i], bf, acc[i][j]);
        }
    }
    __syncthreads();   // all mma reads of Xs/W1s done before aliasing with C1s
#pragma unroll
    for (int i = 0; i < 3; i++)
#pragma unroll
        for (int j = 0; j < 6; j++)
            wmma::store_matrix_sync(C1s + (mrow0 + i * 16) * 388 + ncol0 + j * 16,
                                    acc[i][j], 388, wmma::mem_row_major);
    __syncthreads();

    // ---- bias + gelu -> A1s (fp16) ----
    for (int e = t; e < TILE_M * D_; e += 256) {
        int m = e / D_, n = e - m * D_;
        float v = C1s[m * 388 + n] + fb1[n];
        A1s[m * 392 + n] = __float2half_rn(geluf(v));
    }
    __syncthreads();   // C1s dead; chunk buffers may overwrite

    // ---- GEMM2: [96,384] @ [384,384], W2 streamed in 6 chunks of k=64 ----
#pragma unroll
    for (int i = 0; i < 3; i++)
#pragma unroll
        for (int j = 0; j < 6; j++) wmma::fill_fragment(acc[i][j], 0.0f);

    auto load_chunk = [&](int c, __half* dst) {
        const __half* src = g_W2h + (size_t)c * 64 * D_;
        for (int q = t; q < 3072; q += 256) {         // 64 rows x 48 x 16B
            int r = q / 48, c8 = q - r * 48;
            cp_async16(dst + r * 392 + c8 * 8, src + r * 384 + c8 * 8);
        }
    };
    load_chunk(0, chk0);
    cp_commit(); cp_wait0();
    __syncthreads();

    for (int c = 0; c < 6; c++) {
        __half* cur = (c & 1) ? chk1 : chk0;
        if (c < 5) { load_chunk(c + 1, (c & 1) ? chk0 : chk1); cp_commit(); }
#pragma unroll
        for (int ks = 0; ks < 4; ks++) {
            int k2 = c * 64 + ks * 16;
            wmma::fragment<wmma::matrix_a, 16, 16, 16, __half, wmma::row_major> af[3];
#pragma unroll
            for (int i = 0; i < 3; i++)
                wmma::load_matrix_sync(af[i], A1s + (mrow0 + i * 16) * 392 + k2, 392);
#pragma unroll
            for (int j = 0; j < 6; j++) {
                wmma::fragment<wmma::matrix_b, 16, 16, 16, __half, wmma::row_major> bf;
                wmma::load_matrix_sync(bf, cur + (ks * 16) * 392 + ncol0 + j * 16, 392);
#pragma unroll
                for (int i = 0; i < 3; i++) wmma::mma_sync(acc[i][j], af[i], bf, acc[i][j]);
            }
        }
        if (c < 5) cp_wait0();
        __syncthreads();
    }

    // ---- store C2, then fused bias+gelu+gather+K-reduce epilogue ----
#pragma unroll
    for (int i = 0; i < 3; i++)
#pragma unroll
        for (int j = 0; j < 6; j++)
            wmma::store_matrix_sync(C2s + (mrow0 + i * 16) * 388 + ncol0 + j * 16,
                                    acc[i][j], 388, wmma::mem_row_major);
    __syncthreads();

    {
        const int n0 = t;                 // < 256
        const int n1 = 256 + t;           // valid when t < 128
        const bool has1 = (t < 128);
        float fa = fb2[n0];
        float fbv = has1 ? fb2[n1] : 0.0f;
        const float* hVb = h_V + (size_t)b * L_ * D_;

        float a00 = 0.f, a01 = 0.f, a10 = 0.f, a11 = 0.f;
#pragma unroll 4
        for (int m = 0; m < 48; m++) {
            const float* xr = hVb + (size_t)idxs[m] * D_;
            float w0 = geluf(C2s[m * 388 + n0] + fa);
            a00 += w0 * xr[n0];
            if (has1) { float w1 = geluf(C2s[m * 388 + n1] + fbv); a01 += w1 * xr[n1]; }
        }
#pragma unroll 4
        for (int m = 48; m < 96; m++) {
            const float* xr = hVb + (size_t)idxs[m] * D_;
            float w0 = geluf(C2s[m * 388 + n0] + fa);
            a10 += w0 * xr[n0];
            if (has1) { float w1 = geluf(C2s[m * 388 + n1] + fbv); a11 += w1 * xr[n1]; }
        }
        const size_t g0 = (size_t)tile * 2;
        g_hbuf[g0 * D_ + n0] = a00;
        g_hbuf[(g0 + 1) * D_ + n0] = a10;
        if (has1) {
            g_hbuf[g0 * D_ + n1] = a01;
            g_hbuf[(g0 + 1) * D_ + n1] = a11;
        }
    }
}

// ============================================================
// head MLP: h[8192,384] -> gelu(@hw1) -> gelu(@hw2) -> @hw3 -> dG[8192]
// one CTA = 64 rows, 256 threads
// ============================================================
__global__ void __launch_bounds__(256, 1)
k_head(const float* __restrict__ hw1, const float* __restrict__ hb1,
       const float* __restrict__ hw2, const float* __restrict__ hb2,
       const float* __restrict__ hw3, const float* __restrict__ hb3)
{
    extern __shared__ unsigned char sm[];
    float* hs  = (float*)(sm + HOFF_HS);   // [64][388]
    float* h1s = (float*)(sm + HOFF_H1);   // [64][132]
    float* h2s = (float*)(sm + HOFF_H2);   // [64][65]
    const int t = threadIdx.x;
    const int row0 = blockIdx.x * 64;

    for (int e = t; e < 64 * D_; e += 256) {
        int r = e / D_, n = e - r * D_;
        hs[r * 388 + n] = g_hbuf[(size_t)(row0 + r) * D_ + n];
    }
    __syncthreads();

    // hidden1: unit u = t%128, rows block rb = t/128 (32 rows each)
    {
        const int u = t & 127, rb = t >> 7;
        float accv[32];
#pragma unroll
        for (int r = 0; r < 32; r++) accv[r] = 0.f;
        const float* hb = hs + (rb * 32) * 388;
        for (int d0 = 0; d0 < D_; d0 += 4) {
            float w0 = hw1[(d0 + 0) * H_ + u];
            float w1 = hw1[(d0 + 1) * H_ + u];
            float w2 = hw1[(d0 + 2) * H_ + u];
            float w3 = hw1[(d0 + 3) * H_ + u];
#pragma unroll
            for (int r = 0; r < 32; r++) {
                float4 hv = *reinterpret_cast<const float4*>(hb + r * 388 + d0);
                accv[r] += hv.x * w0 + hv.y * w1 + hv.z * w2 + hv.w * w3;
            }
        }
        float b1 = hb1[u];
#pragma unroll
        for (int r = 0; r < 32; r++) h1s[(rb * 32 + r) * 132 + u] = geluf(accv[r] + b1);
    }
    __syncthreads();

    // hidden2: unit u = t%64, rows block rb = t/64 (16 rows each)
    {
        const int u = t & 63, rb = t >> 6;
        float accv[16];
#pragma unroll
        for (int r = 0; r < 16; r++) accv[r] = 0.f;
        const float* hb = h1s + (rb * 16) * 132;
        for (int d0 = 0; d0 < H_; d0 += 4) {
            float w0 = hw2[(d0 + 0) * 64 + u];
            float w1 = hw2[(d0 + 1) * 64 + u];
            float w2 = hw2[(d0 + 2) * 64 + u];
            float w3 = hw2[(d0 + 3) * 64 + u];
#pragma unroll
            for (int r = 0; r < 16; r++) {
                float4 hv = *reinterpret_cast<const float4*>(hb + r * 132 + d0);
                accv[r] += hv.x * w0 + hv.y * w1 + hv.z * w2 + hv.w * w3;
            }
        }
        float b2 = hb2[u];
#pragma unroll
        for (int r = 0; r < 16; r++) h2s[(rb * 16 + r) * 65 + u] = geluf(accv[r] + b2);
    }
    __syncthreads();

    if (t < 64) {
        float s = hb3[0];
#pragma unroll 8
        for (int j = 0; j < 64; j++) s += h2s[t * 65 + j] * hw3[j];
        g_dG[row0 + t] = s;
    }
}

// ============================================================
// masked mean over L, per batch
// ============================================================
__global__ void k_final(const float* __restrict__ mask, float* __restrict__ out) {
    const int w = threadIdx.x >> 5, lane = threadIdx.x & 31;
    if (w < B_) {
        float s = 0.f, ms = 0.f;
        for (int l = lane; l < L_; l += 32) {
            float mk = mask[w * L_ + l];
            s  += g_dG[w * L_ + l] * mk;
            ms += mk;
        }
#pragma unroll
        for (int o = 16; o; o >>= 1) {
            s  += __shfl_down_sync(0xffffffff, s, o);
            ms += __shfl_down_sync(0xffffffff, ms, o);
        }
        if (lane == 0) out[w] = s / sqrtf(fmaxf(ms, 1.0f));
    }
}

// ============================================================
extern "C" void kernel_launch(void* const* d_in, const int* in_sizes, int n_in,
                              void* d_out, int out_size)
{
    const float* h_V  = (const float*)d_in[0];
    const float* h_E  = (const float*)d_in[1];
    const float* mask = (const float*)d_in[2];
    const float* fw1  = (const float*)d_in[3];
    const float* fb1  = (const float*)d_in[4];
    const float* fw2  = (const float*)d_in[5];
    const float* fb2  = (const float*)d_in[6];
    const float* hw1  = (const float*)d_in[7];
    const float* hb1  = (const float*)d_in[8];
    const float* hw2  = (const float*)d_in[9];
    const float* hb2  = (const float*)d_in[10];
    const float* hw3  = (const float*)d_in[11];
    const float* hb3  = (const float*)d_in[12];
    const int*   E_idx = (const int*)d_in[13];
    float* out = (float*)d_out;

    cudaFuncSetAttribute(k_main, cudaFuncAttributeMaxDynamicSharedMemorySize, SMEM_MAIN);
    cudaFuncSetAttribute(k_head, cudaFuncAttributeMaxDynamicSharedMemorySize, SMEM_HEAD);

    k_convert<<<192, 256>>>(fw1, fw2);
    k_main<<<NTILES, 256, SMEM_MAIN>>>(h_V, h_E, fb1, fb2, E_idx);
    k_head<<<B_ * L_ / 64, 256, SMEM_HEAD>>>(hw1, hb1, hw2, hb2, hw3, hb3);
    k_final<<<1, 512>>>(mask, out);
}

// round 5
// speedup vs baseline: 1.5231x; 1.5231x over previous
#include <cuda_runtime.h>
#include <cuda_fp16.h>
#include <mma.h>
#include <cstdint>

using namespace nvcuda;

// Problem dims
#define B_  16
#define L_  512
#define Kn_ 48
#define E_  128
#define D_  384
#define H_  128

#define TILE_M  96
#define NTILES  4096          // (B*L*K)/TILE_M
#define NTHREADS 512

// ---- smem layout (bytes) for k_main (identical to round-1 known-good plan) ----
#define OFF_A1S   0            // [96][392] half
#define OFF_XS    75264        // [96][136] half
#define OFF_W1S   101376       // [128][392] half
#define OFF_C1S   75264        // alias (after GEMM1; Xs/W1s dead) [96][388] f32
#define OFF_CHK0  76800        // alias [64][392] half
#define OFF_CHK1  126976       // alias [64][392] half
#define OFF_C2S   76800        // alias [96][388] f32 (after GEMM2)
#define OFF_IDX   225792       // 96 ints
#define SMEM_MAIN 226304

// head kernel smem
#define HOFF_HS   0
#define HOFF_H1   99328
#define HOFF_H2   133120
#define SMEM_HEAD 149760

__device__ __align__(16) __half g_W1h[E_ * D_];
__device__ __align__(16) __half g_W2h[D_ * D_];
__device__ __align__(16) float  g_hbuf[(size_t)B_ * L_ * D_];
__device__ __align__(16) float  g_dG[B_ * L_];

__device__ __forceinline__ float geluf(float x) {
    return 0.5f * x * (1.0f + erff(x * 0.7071067811865476f));
}

__device__ __forceinline__ void cp_async16(void* dst, const void* src) {
    unsigned s = (unsigned)__cvta_generic_to_shared(dst);
    asm volatile("cp.async.cg.shared.global [%0], [%1], 16;\n" :: "r"(s), "l"(src) : "memory");
}
__device__ __forceinline__ void cp_commit() { asm volatile("cp.async.commit_group;\n" ::: "memory"); }
__device__ __forceinline__ void cp_wait0()  { asm volatile("cp.async.wait_group 0;\n" ::: "memory"); }

// ============================================================
__global__ void k_convert(const float* __restrict__ fw1, const float* __restrict__ fw2) {
    int stride = gridDim.x * blockDim.x;
    int i0 = blockIdx.x * blockDim.x + threadIdx.x;
    for (int q = i0; q < E_ * D_; q += stride) g_W1h[q] = __float2half_rn(fw1[q]);
    for (int q = i0; q < D_ * D_; q += stride) g_W2h[q] = __float2half_rn(fw2[q]);
}

// ============================================================
// fused: GEMM1 + gelu + GEMM2 + gelu + gather + K-reduce
// 512 threads = 16 warps in 2(m) x 8(n); warp tile 48 x 48
// ============================================================
__global__ void __launch_bounds__(NTHREADS, 1)
k_main(const float* __restrict__ h_V, const float* __restrict__ h_E,
       const float* __restrict__ fb1, const float* __restrict__ fb2,
       const int* __restrict__ E_idx)
{
    extern __shared__ unsigned char smem[];
    __half* A1s  = (__half*)(smem + OFF_A1S);
    __half* Xs   = (__half*)(smem + OFF_XS);
    __half* W1s  = (__half*)(smem + OFF_W1S);
    float*  C1s  = (float*)(smem + OFF_C1S);
    float*  C2s  = (float*)(smem + OFF_C2S);
    __half* chk0 = (__half*)(smem + OFF_CHK0);
    __half* chk1 = (__half*)(smem + OFF_CHK1);
    int*    idxs = (int*)(smem + OFF_IDX);

    const int t = threadIdx.x;
    const int tile = blockIdx.x;
    const int rowbase = tile * TILE_M;
    const int b = rowbase / (L_ * Kn_);

    if (t < TILE_M) idxs[t] = E_idx[rowbase + t];

    // ---- stage W1 (cp.async) and X tile (fp32->fp16) ----
    for (int q = t; q < (E_ * D_) / 8; q += NTHREADS) {      // 6144 x 16B
        int r = q / 48, c8 = q - r * 48;
        cp_async16(W1s + r * 392 + c8 * 8, g_W1h + r * 384 + c8 * 8);
    }
    cp_commit();
    {
        const float4* Xg = reinterpret_cast<const float4*>(h_E + (size_t)rowbase * E_);
        for (int q = t; q < (TILE_M * E_) / 4; q += NTHREADS) {
            int m = q >> 5, c4 = q & 31;
            float4 v = Xg[q];
            __half2* d = reinterpret_cast<__half2*>(Xs + m * 136 + c4 * 4);
            d[0] = __floats2half2_rn(v.x, v.y);
            d[1] = __floats2half2_rn(v.z, v.w);
        }
    }
    cp_wait0();
    __syncthreads();

    // 16 warps: 2(m) x 8(n); warp tile 48 x 48 -> 3x3 fragments
    const int warp  = t >> 5;
    const int wm    = warp >> 3;     // 0..1
    const int wn    = warp & 7;      // 0..7
    const int mrow0 = wm * 48;
    const int ncol0 = wn * 48;

    wmma::fragment<wmma::accumulator, 16, 16, 16, float> acc[3][3];
#pragma unroll
    for (int i = 0; i < 3; i++)
#pragma unroll
        for (int j = 0; j < 3; j++) wmma::fill_fragment(acc[i][j], 0.0f);

    // ---- GEMM1: [96,128] @ [128,384] ----
#pragma unroll
    for (int k = 0; k < E_; k += 16) {
        wmma::fragment<wmma::matrix_a, 16, 16, 16, __half, wmma::row_major> af[3];
#pragma unroll
        for (int i = 0; i < 3; i++)
            wmma::load_matrix_sync(af[i], Xs + (mrow0 + i * 16) * 136 + k, 136);
#pragma unroll
        for (int j = 0; j < 3; j++) {
            wmma::fragment<wmma::matrix_b, 16, 16, 16, __half, wmma::row_major> bf;
            wmma::load_matrix_sync(bf, W1s + k * 392 + ncol0 + j * 16, 392);
#pragma unroll
            for (int i = 0; i < 3; i++) wmma::mma_sync(acc[i][j], af[i], bf, acc[i][j]);
        }
    }
    __syncthreads();   // mma reads of Xs/W1s done before aliasing with C1s
#pragma unroll
    for (int i = 0; i < 3; i++)
#pragma unroll
        for (int j = 0; j < 3; j++)
            wmma::store_matrix_sync(C1s + (mrow0 + i * 16) * 388 + ncol0 + j * 16,
                                    acc[i][j], 388, wmma::mem_row_major);
    __syncthreads();

    // ---- bias + gelu -> A1s (fp16) ----
    for (int e = t; e < TILE_M * D_; e += NTHREADS) {
        int m = e / D_, n = e - m * D_;
        float v = C1s[m * 388 + n] + fb1[n];
        A1s[m * 392 + n] = __float2half_rn(geluf(v));
    }
    __syncthreads();   // C1s dead; chunk buffers may overwrite

    // ---- GEMM2: [96,384] @ [384,384], W2 streamed in 6 chunks of k=64 ----
#pragma unroll
    for (int i = 0; i < 3; i++)
#pragma unroll
        for (int j = 0; j < 3; j++) wmma::fill_fragment(acc[i][j], 0.0f);

    auto load_chunk = [&](int c, __half* dst) {
        const __half* src = g_W2h + (size_t)c * 64 * D_;
        for (int q = t; q < 3072; q += NTHREADS) {     // 64 rows x 48 x 16B
            int r = q / 48, c8 = q - r * 48;
            cp_async16(dst + r * 392 + c8 * 8, src + r * 384 + c8 * 8);
        }
    };
    load_chunk(0, chk0);
    cp_commit(); cp_wait0();
    __syncthreads();

    for (int c = 0; c < 6; c++) {
        __half* cur = (c & 1) ? chk1 : chk0;
        if (c < 5) { load_chunk(c + 1, (c & 1) ? chk0 : chk1); cp_commit(); }
#pragma unroll
        for (int ks = 0; ks < 4; ks++) {
            int k2 = c * 64 + ks * 16;
            wmma::fragment<wmma::matrix_a, 16, 16, 16, __half, wmma::row_major> af[3];
#pragma unroll
            for (int i = 0; i < 3; i++)
                wmma::load_matrix_sync(af[i], A1s + (mrow0 + i * 16) * 392 + k2, 392);
#pragma unroll
            for (int j = 0; j < 3; j++) {
                wmma::fragment<wmma::matrix_b, 16, 16, 16, __half, wmma::row_major> bf;
                wmma::load_matrix_sync(bf, cur + (ks * 16) * 392 + ncol0 + j * 16, 392);
#pragma unroll
                for (int i = 0; i < 3; i++) wmma::mma_sync(acc[i][j], af[i], bf, acc[i][j]);
            }
        }
        if (c < 5) cp_wait0();
        __syncthreads();
    }

    // ---- store C2, then fused bias+gelu+gather+K-reduce ----
#pragma unroll
    for (int i = 0; i < 3; i++)
#pragma unroll
        for (int j = 0; j < 3; j++)
            wmma::store_matrix_sync(C2s + (mrow0 + i * 16) * 388 + ncol0 + j * 16,
                                    acc[i][j], 388, wmma::mem_row_major);
    __syncthreads();

    // 768 work items: (group g in 0..1) x (col n in 0..383); each sums 48 rows
    {
        const float* hVb = h_V + (size_t)b * L_ * D_;
#pragma unroll
        for (int qi = 0; qi < 2; qi++) {
            int q = t + qi * NTHREADS;
            if (q < 768) {
                int g = q >= 384, n = q - (g ? 384 : 0);
                float fbv = fb2[n];
                float accv = 0.f;
                const int m0 = g * 48;
#pragma unroll 4
                for (int m = m0; m < m0 + 48; m++) {
                    float wv = geluf(C2s[m * 388 + n] + fbv);
                    accv += wv * hVb[(size_t)idxs[m] * D_ + n];
                }
                g_hbuf[(size_t)(tile * 2 + g) * D_ + n] = accv;
            }
        }
    }
}

// ============================================================
// head MLP: h[8192,384] -> gelu(@hw1) -> gelu(@hw2) -> @hw3 -> dG
// ============================================================
__global__ void __launch_bounds__(256, 1)
k_head(const float* __restrict__ hw1, const float* __restrict__ hb1,
       const float* __restrict__ hw2, const float* __restrict__ hb2,
       const float* __restrict__ hw3, const float* __restrict__ hb3)
{
    extern __shared__ unsigned char sm[];
    float* hs  = (float*)(sm + HOFF_HS);
    float* h1s = (float*)(sm + HOFF_H1);
    float* h2s = (float*)(sm + HOFF_H2);
    const int t = threadIdx.x;
    const int row0 = blockIdx.x * 64;

    for (int e = t; e < 64 * D_; e += 256) {
        int r = e / D_, n = e - r * D_;
        hs[r * 388 + n] = g_hbuf[(size_t)(row0 + r) * D_ + n];
    }
    __syncthreads();
    {
        const int u = t & 127, rb = t >> 7;
        float accv[32];
#pragma unroll
        for (int r = 0; r < 32; r++) accv[r] = 0.f;
        const float* hb = hs + (rb * 32) * 388;
        for (int d0 = 0; d0 < D_; d0 += 4) {
            float w0 = hw1[(d0 + 0) * H_ + u], w1 = hw1[(d0 + 1) * H_ + u];
            float w2 = hw1[(d0 + 2) * H_ + u], w3 = hw1[(d0 + 3) * H_ + u];
#pragma unroll
            for (int r = 0; r < 32; r++) {
                float4 hv = *reinterpret_cast<const float4*>(hb + r * 388 + d0);
                accv[r] += hv.x * w0 + hv.y * w1 + hv.z * w2 + hv.w * w3;
            }
        }
        float b1 = hb1[u];
#pragma unroll
        for (int r = 0; r < 32; r++) h1s[(rb * 32 + r) * 132 + u] = geluf(accv[r] + b1);
    }
    __syncthreads();
    {
        const int u = t & 63, rb = t >> 6;
        float accv[16];
#pragma unroll
        for (int r = 0; r < 16; r++) accv[r] = 0.f;
        const float* hb = h1s + (rb * 16) * 132;
        for (int d0 = 0; d0 < H_; d0 += 4) {
            float w0 = hw2[(d0 + 0) * 64 + u], w1 = hw2[(d0 + 1) * 64 + u];
            float w2 = hw2[(d0 + 2) * 64 + u], w3 = hw2[(d0 + 3) * 64 + u];
#pragma unroll
            for (int r = 0; r < 16; r++) {
                float4 hv = *reinterpret_cast<const float4*>(hb + r * 132 + d0);
                accv[r] += hv.x * w0 + hv.y * w1 + hv.z * w2 + hv.w * w3;
            }
        }
        float b2 = hb2[u];
#pragma unroll
        for (int r = 0; r < 16; r++) h2s[(rb * 16 + r) * 65 + u] = geluf(accv[r] + b2);
    }
    __syncthreads();
    if (t < 64) {
        float s = hb3[0];
#pragma unroll 8
        for (int j = 0; j < 64; j++) s += h2s[t * 65 + j] * hw3[j];
        g_dG[row0 + t] = s;
    }
}

// ============================================================
__global__ void k_final(const float* __restrict__ mask, float* __restrict__ out) {
    const int w = threadIdx.x >> 5, lane = threadIdx.x & 31;
    if (w < B_) {
        float s = 0.f, ms = 0.f;
        for (int l = lane; l < L_; l += 32) {
            float mk = mask[w * L_ + l];
            s  += g_dG[w * L_ + l] * mk;
            ms += mk;
        }
#pragma unroll
        for (int o = 16; o; o >>= 1) {
            s  += __shfl_down_sync(0xffffffff, s, o);
            ms += __shfl_down_sync(0xffffffff, ms, o);
        }
        if (lane == 0) out[w] = s / sqrtf(fmaxf(ms, 1.0f));
    }
}

// ============================================================
extern "C" void kernel_launch(void* const* d_in, const int* in_sizes, int n_in,
                              void* d_out, int out_size)
{
    const float* h_V  = (const float*)d_in[0];
    const float* h_E  = (const float*)d_in[1];
    const float* mask = (const float*)d_in[2];
    const float* fw1  = (const float*)d_in[3];
    const float* fb1  = (const float*)d_in[4];
    const float* fw2  = (const float*)d_in[5];
    const float* fb2  = (const float*)d_in[6];
    const float* hw1  = (const float*)d_in[7];
    const float* hb1  = (const float*)d_in[8];
    const float* hw2  = (const float*)d_in[9];
    const float* hb2  = (const float*)d_in[10];
    const float* hw3  = (const float*)d_in[11];
    const float* hb3  = (const float*)d_in[12];
    const int*   E_idx = (const int*)d_in[13];
    float* out = (float*)d_out;

    cudaFuncSetAttribute(k_main, cudaFuncAttributeMaxDynamicSharedMemorySize, SMEM_MAIN);
    cudaFuncSetAttribute(k_head, cudaFuncAttributeMaxDynamicSharedMemorySize, SMEM_HEAD);

    k_convert<<<192, 256>>>(fw1, fw2);
    k_main<<<NTILES, NTHREADS, SMEM_MAIN>>>(h_V, h_E, fb1, fb2, E_idx);
    k_head<<<B_ * L_ / 64, 256, SMEM_HEAD>>>(hw1, hb1, hw2, hb2, hw3, hb3);
    k_final<<<1, 512>>>(mask, out);
}

// round 7
// speedup vs baseline: 1.6310x; 1.0708x over previous
#include <cuda_runtime.h>
#include <cuda_fp16.h>
#include <cstdint>

#define B_  16
#define L_  512
#define Kn_ 48
#define E_  128
#define D_  384
#define H_  128

#define TILE_M  96
#define NTILES  4096
#define NTHREADS 512

// ---- smem layout (bytes) ----
// A1s [96][392] half : [0, 75264)                      (GEMM1 out, GEMM2 in)
// Xs  [96][136] half : [75264, 101376)                 (dead after GEMM1 mainloop)
// W1s [128][392]half : [101376, 201728)                (dead after GEMM1 mainloop)
// chk0 [96][392]half : alias [75264, 150528)           (live during GEMM2)
// chk1 [96][392]half : alias [150528, 225792)
// C2s [96][388] f32  : alias [75264, 224256)           (after GEMM2 mainloop)
// idxs 96 int        : [225792, 226176)
#define OFF_A1S   0
#define OFF_XS    75264
#define OFF_W1S   101376
#define OFF_CHK0  75264
#define OFF_CHK1  150528
#define OFF_C2S   75264
#define C2P       388
#define OFF_IDX   225792
#define SMEM_MAIN 226304

#define HOFF_HS   0
#define HOFF_H1   99328
#define HOFF_H2   133120
#define SMEM_HEAD 149760

__device__ __align__(16) __half g_W1h[E_ * D_];
__device__ __align__(16) __half g_W2h[D_ * D_];
__device__ __align__(16) float  g_hbuf[(size_t)B_ * L_ * D_];
__device__ __align__(16) float  g_dG[B_ * L_];

__device__ __forceinline__ float geluf(float x) {
    return 0.5f * x * (1.0f + erff(x * 0.7071067811865476f));
}
__device__ __forceinline__ uint32_t smem_u32(const void* p) {
    uint32_t a;
    asm("{ .reg .u64 t; cvta.to.shared.u64 t, %1; cvt.u32.u64 %0, t; }" : "=r"(a) : "l"(p));
    return a;
}
__device__ __forceinline__ void cp_async16(uint32_t dst, const void* src) {
    asm volatile("cp.async.cg.shared.global [%0], [%1], 16;\n" :: "r"(dst), "l"(src) : "memory");
}
__device__ __forceinline__ void cp_commit() { asm volatile("cp.async.commit_group;\n" ::: "memory"); }
__device__ __forceinline__ void cp_wait0()  { asm volatile("cp.async.wait_group 0;\n" ::: "memory"); }

__device__ __forceinline__ void ldsm4(uint32_t* r, uint32_t addr) {
    asm volatile("ldmatrix.sync.aligned.m8n8.x4.shared.b16 {%0,%1,%2,%3}, [%4];"
        : "=r"(r[0]), "=r"(r[1]), "=r"(r[2]), "=r"(r[3]) : "r"(addr));
}
__device__ __forceinline__ void ldsm2t(uint32_t& b0, uint32_t& b1, uint32_t addr) {
    asm volatile("ldmatrix.sync.aligned.m8n8.x2.trans.shared.b16 {%0,%1}, [%2];"
        : "=r"(b0), "=r"(b1) : "r"(addr));
}
__device__ __forceinline__ void mma16816(float* c, const uint32_t* a, uint32_t b0, uint32_t b1) {
    asm volatile("mma.sync.aligned.m16n8k16.row.col.f32.f16.f16.f32 "
        "{%0,%1,%2,%3}, {%4,%5,%6,%7}, {%8,%9}, {%0,%1,%2,%3};"
        : "+f"(c[0]), "+f"(c[1]), "+f"(c[2]), "+f"(c[3])
        : "r"(a[0]), "r"(a[1]), "r"(a[2]), "r"(a[3]), "r"(b0), "r"(b1));
}

// ============================================================
__global__ void k_convert(const float* __restrict__ fw1, const float* __restrict__ fw2) {
    int stride = gridDim.x * blockDim.x;
    int i0 = blockIdx.x * blockDim.x + threadIdx.x;
    for (int q = i0; q < E_ * D_; q += stride) g_W1h[q] = __float2half_rn(fw1[q]);
    for (int q = i0; q < D_ * D_; q += stride) g_W2h[q] = __float2half_rn(fw2[q]);
}

// ============================================================
// fused main: raw mma.sync, register epilogues
// 16 warps: 2(m) x 8(n); warp tile m48 x n48 (3 m16 x 6 n8)
// ============================================================
__global__ void __launch_bounds__(NTHREADS, 1)
k_main(const float* __restrict__ h_V, const float* __restrict__ h_E,
       const float* __restrict__ fb1, const float* __restrict__ fb2,
       const int* __restrict__ E_idx)
{
    extern __shared__ __align__(16) unsigned char smem[];
    const uint32_t sbase = smem_u32(smem);
    __half* A1s = (__half*)(smem + OFF_A1S);
    float*  C2s = (float*)(smem + OFF_C2S);
    int*    idxs = (int*)(smem + OFF_IDX);

    const int t = threadIdx.x;
    const int warp = t >> 5, lane = t & 31;
    const int tile = blockIdx.x;
    const int rowbase = tile * TILE_M;
    const int b = rowbase / (L_ * Kn_);

    if (t < TILE_M) idxs[t] = E_idx[rowbase + t];

    // ---- stage W1 (cp.async) ----
    for (int q = t; q < (E_ * D_) / 8; q += NTHREADS) {     // 6144 x 16B
        int r = q / 48, c8 = q - r * 48;
        cp_async16(sbase + OFF_W1S + (r * 392 + c8 * 8) * 2, g_W1h + r * 384 + c8 * 8);
    }
    cp_commit();
    // ---- stage X tile fp32 -> fp16, stride 136 halfs ----
    {
        const float4* Xg = reinterpret_cast<const float4*>(h_E + (size_t)rowbase * E_);
        __half* Xs = (__half*)(smem + OFF_XS);
        for (int q = t; q < (TILE_M * E_) / 4; q += NTHREADS) {
            int m = q >> 5, c4 = q & 31;
            float4 v = Xg[q];
            __half2* d = reinterpret_cast<__half2*>(Xs + m * 136 + c4 * 4);
            d[0] = __floats2half2_rn(v.x, v.y);
            d[1] = __floats2half2_rn(v.z, v.w);
        }
    }
    cp_wait0();
    __syncthreads();

    const int wm = warp >> 3;           // 0..1
    const int wn = warp & 7;            // 0..7
    const int mrow0 = wm * 48;
    const int ncol0 = wn * 48;
    const int g = lane >> 2, l2 = (lane & 3) * 2;

    float acc[3][6][4];
    #pragma unroll
    for (int i = 0; i < 3; i++)
        #pragma unroll
        for (int j = 0; j < 6; j++)
            #pragma unroll
            for (int r = 0; r < 4; r++) acc[i][j][r] = 0.f;

    // ---- GEMM1: Xs[96][128]@W1s[128][384] ----
    {
        const uint32_t aBase = sbase + OFF_XS + (uint32_t)(mrow0 + (lane & 15)) * 272 + ((lane >> 4) << 4);
        const uint32_t bBase = sbase + OFF_W1S + (uint32_t)(lane & 15) * 784 + (uint32_t)ncol0 * 2;
        #pragma unroll
        for (int ks = 0; ks < 8; ks++) {
            uint32_t a[3][4];
            #pragma unroll
            for (int i = 0; i < 3; i++) ldsm4(a[i], aBase + i * 4352 + ks * 32);
            #pragma unroll
            for (int j = 0; j < 6; j++) {
                uint32_t b0, b1;
                ldsm2t(b0, b1, bBase + j * 16 + ks * 12544);
                #pragma unroll
                for (int i = 0; i < 3; i++) mma16816(acc[i][j], a[i], b0, b1);
            }
        }
    }
    __syncthreads();                    // Xs/W1s dead; chunk region free

    // ---- kick off W2 chunk 0 load (overlaps epilogue) ----
    {
        const __half* src = g_W2h;      // rows 0..95
        for (int q = t; q < 96 * 48; q += NTHREADS) {
            int r = q / 48, c8 = q - r * 48;
            cp_async16(sbase + OFF_CHK0 + (r * 392 + c8 * 8) * 2, src + r * 384 + c8 * 8);
        }
        cp_commit();
    }

    // ---- GEMM1 epilogue in registers: +fb1, gelu, fp16 -> A1s ----
    #pragma unroll
    for (int i = 0; i < 3; i++) {
        int r0 = mrow0 + i * 16 + g;
        #pragma unroll
        for (int j = 0; j < 6; j++) {
            int col = ncol0 + j * 8 + l2;
            float bb0 = __ldg(fb1 + col), bb1 = __ldg(fb1 + col + 1);
            *reinterpret_cast<__half2*>(A1s + r0 * 392 + col) =
                __floats2half2_rn(geluf(acc[i][j][0] + bb0), geluf(acc[i][j][1] + bb1));
            *reinterpret_cast<__half2*>(A1s + (r0 + 8) * 392 + col) =
                __floats2half2_rn(geluf(acc[i][j][2] + bb0), geluf(acc[i][j][3] + bb1));
        }
    }
    #pragma unroll
    for (int i = 0; i < 3; i++)
        #pragma unroll
        for (int j = 0; j < 6; j++)
            #pragma unroll
            for (int r = 0; r < 4; r++) acc[i][j][r] = 0.f;
    cp_wait0();
    __syncthreads();                    // chunk0 ready, A1s complete

    // ---- GEMM2: A1s[96][384]@W2[384][384], 4 chunks of k=96 ----
    {
        const uint32_t aBase = sbase + OFF_A1S + (uint32_t)(mrow0 + (lane & 15)) * 784 + ((lane >> 4) << 4);
        const uint32_t bRow = (uint32_t)(lane & 15) * 784 + (uint32_t)ncol0 * 2;
        for (int c = 0; c < 4; c++) {
            if (c < 3) {                // prefetch chunk c+1 into other buffer
                const __half* src = g_W2h + (size_t)(c + 1) * 96 * D_;
                uint32_t dst = sbase + (((c + 1) & 1) ? OFF_CHK1 : OFF_CHK0);
                for (int q = t; q < 96 * 48; q += NTHREADS) {
                    int r = q / 48, c8 = q - r * 48;
                    cp_async16(dst + (r * 392 + c8 * 8) * 2, src + r * 384 + c8 * 8);
                }
                cp_commit();
            }
            const uint32_t bBase = sbase + ((c & 1) ? OFF_CHK1 : OFF_CHK0) + bRow;
            const uint32_t aOff = aBase + c * 192;          // c*96 halfs = 192B
            #pragma unroll
            for (int ks = 0; ks < 6; ks++) {
                uint32_t a[3][4];
                #pragma unroll
                for (int i = 0; i < 3; i++) ldsm4(a[i], aOff + i * 12544 + ks * 32); // 16 rows x 784B
                #pragma unroll
                for (int j = 0; j < 6; j++) {
                    uint32_t b0, b1;
                    ldsm2t(b0, b1, bBase + j * 16 + ks * 12544);
                    #pragma unroll
                    for (int i = 0; i < 3; i++) mma16816(acc[i][j], a[i], b0, b1);
                }
            }
            if (c < 3) cp_wait0();
            __syncthreads();
        }
    }

    // ---- GEMM2 epilogue: +fb2, gelu, fp32 -> C2s (chunks dead) ----
    #pragma unroll
    for (int i = 0; i < 3; i++) {
        int r0 = mrow0 + i * 16 + g;
        #pragma unroll
        for (int j = 0; j < 6; j++) {
            int col = ncol0 + j * 8 + l2;
            float bb0 = __ldg(fb2 + col), bb1 = __ldg(fb2 + col + 1);
            float2 v0 = make_float2(geluf(acc[i][j][0] + bb0), geluf(acc[i][j][1] + bb1));
            float2 v1 = make_float2(geluf(acc[i][j][2] + bb0), geluf(acc[i][j][3] + bb1));
            *reinterpret_cast<float2*>(C2s + r0 * C2P + col) = v0;
            *reinterpret_cast<float2*>(C2s + (r0 + 8) * C2P + col) = v1;
        }
    }
    __syncthreads();

    // ---- gather x_j + K-reduce: 768 items = 2 groups x 384 cols ----
    {
        const float* hVb = h_V + (size_t)b * L_ * D_;
        #pragma unroll
        for (int qi = 0; qi < 2; qi++) {
            int q = t + qi * NTHREADS;
            if (q < 768) {
                int gg = q >= 384, n = q - (gg ? 384 : 0);
                float accv = 0.f;
                const int m0 = gg * 48;
                #pragma unroll 4
                for (int m = m0; m < m0 + 48; m++)
                    accv += C2s[m * C2P + n] * hVb[(size_t)idxs[m] * D_ + n];
                g_hbuf[(size_t)(tile * 2 + gg) * D_ + n] = accv;
            }
        }
    }
}

// ============================================================
__global__ void __launch_bounds__(256, 1)
k_head(const float* __restrict__ hw1, const float* __restrict__ hb1,
       const float* __restrict__ hw2, const float* __restrict__ hb2,
       const float* __restrict__ hw3, const float* __restrict__ hb3)
{
    extern __shared__ unsigned char sm[];
    float* hs  = (float*)(sm + HOFF_HS);
    float* h1s = (float*)(sm + HOFF_H1);
    float* h2s = (float*)(sm + HOFF_H2);
    const int t = threadIdx.x;
    const int row0 = blockIdx.x * 64;

    for (int e = t; e < 64 * D_; e += 256) {
        int r = e / D_, n = e - r * D_;
        hs[r * 388 + n] = g_hbuf[(size_t)(row0 + r) * D_ + n];
    }
    __syncthreads();
    {
        const int u = t & 127, rb = t >> 7;
        float accv[32];
        #pragma unroll
        for (int r = 0; r < 32; r++) accv[r] = 0.f;
        const float* hb = hs + (rb * 32) * 388;
        for (int d0 = 0; d0 < D_; d0 += 4) {
            float w0 = hw1[(d0 + 0) * H_ + u], w1 = hw1[(d0 + 1) * H_ + u];
            float w2 = hw1[(d0 + 2) * H_ + u], w3 = hw1[(d0 + 3) * H_ + u];
            #pragma unroll
            for (int r = 0; r < 32; r++) {
                float4 hv = *reinterpret_cast<const float4*>(hb + r * 388 + d0);
                accv[r] += hv.x * w0 + hv.y * w1 + hv.z * w2 + hv.w * w3;
            }
        }
        float b1 = hb1[u];
        #pragma unroll
        for (int r = 0; r < 32; r++) h1s[(rb * 32 + r) * 132 + u] = geluf(accv[r] + b1);
    }
    __syncthreads();
    {
        const int u = t & 63, rb = t >> 6;
        float accv[16];
        #pragma unroll
        for (int r = 0; r < 16; r++) accv[r] = 0.f;
        const float* hb = h1s + (rb * 16) * 132;
        for (int d0 = 0; d0 < H_; d0 += 4) {
            float w0 = hw2[(d0 + 0) * 64 + u], w1 = hw2[(d0 + 1) * 64 + u];
            float w2 = hw2[(d0 + 2) * 64 + u], w3 = hw2[(d0 + 3) * 64 + u];
            #pragma unroll
            for (int r = 0; r < 16; r++) {
                float4 hv = *reinterpret_cast<const float4*>(hb + r * 132 + d0);
                accv[r] += hv.x * w0 + hv.y * w1 + hv.z * w2 + hv.w * w3;
            }
        }
        float b2 = hb2[u];
        #pragma unroll
        for (int r = 0; r < 16; r++) h2s[(rb * 16 + r) * 65 + u] = geluf(accv[r] + b2);
    }
    __syncthreads();
    if (t < 64) {
        float s = hb3[0];
        #pragma unroll 8
        for (int j = 0; j < 64; j++) s += h2s[t * 65 + j] * hw3[j];
        g_dG[row0 + t] = s;
    }
}

// ============================================================
__global__ void k_final(const float* __restrict__ mask, float* __restrict__ out) {
    const int w = threadIdx.x >> 5, lane = threadIdx.x & 31;
    if (w < B_) {
        float s = 0.f, ms = 0.f;
        for (int l = lane; l < L_; l += 32) {
            float mk = mask[w * L_ + l];
            s  += g_dG[w * L_ + l] * mk;
            ms += mk;
        }
        #pragma unroll
        for (int o = 16; o; o >>= 1) {
            s  += __shfl_down_sync(0xffffffff, s, o);
            ms += __shfl_down_sync(0xffffffff, ms, o);
        }
        if (lane == 0) out[w] = s / sqrtf(fmaxf(ms, 1.0f));
    }
}

// ============================================================
extern "C" void kernel_launch(void* const* d_in, const int* in_sizes, int n_in,
                              void* d_out, int out_size)
{
    const float* h_V  = (const float*)d_in[0];
    const float* h_E  = (const float*)d_in[1];
    const float* mask = (const float*)d_in[2];
    const float* fw1  = (const float*)d_in[3];
    const float* fb1  = (const float*)d_in[4];
    const float* fw2  = (const float*)d_in[5];
    const float* fb2  = (const float*)d_in[6];
    const float* hw1  = (const float*)d_in[7];
    const float* hb1  = (const float*)d_in[8];
    const float* hw2  = (const float*)d_in[9];
    const float* hb2  = (const float*)d_in[10];
    const float* hw3  = (const float*)d_in[11];
    const float* hb3  = (const float*)d_in[12];
    const int*   E_idx = (const int*)d_in[13];
    float* out = (float*)d_out;

    cudaFuncSetAttribute(k_main, cudaFuncAttributeMaxDynamicSharedMemorySize, SMEM_MAIN);
    cudaFuncSetAttribute(k_head, cudaFuncAttributeMaxDynamicSharedMemorySize, SMEM_HEAD);

    k_convert<<<192, 256>>>(fw1, fw2);
    k_main<<<NTILES, NTHREADS, SMEM_MAIN>>>(h_V, h_E, fb1, fb2, E_idx);
    k_head<<<B_ * L_ / 64, 256, SMEM_HEAD>>>(hw1, hb1, hw2, hb2, hw3, hb3);
    k_final<<<1, 512>>>(mask, out);
}

// round 8
// speedup vs baseline: 1.9362x; 1.1871x over previous
#include <cuda_runtime.h>
#include <cuda_fp16.h>
#include <cstdint>

#define B_  16
#define L_  512
#define Kn_ 48
#define E_  128
#define D_  384
#define H_  128

#define TILE_M  96
#define NTILES  4096
#define NTHREADS 768

// ---- smem layout (bytes) ----
// A1s [96][392] half : [0, 75264)                      (GEMM1 out, GEMM2 in)
// Xs  [96][136] half : [75264, 101376)                 (dead after GEMM1 mainloop)
// W1s [128][392]half : [101376, 201728)                (dead after GEMM1 mainloop)
// chk0 [96][392]half : alias [75264, 150528)           (live during GEMM2)
// chk1 [96][392]half : alias [150528, 225792)
// idxs 96 int        : [225792, 226176)
#define OFF_A1S   0
#define OFF_XS    75264
#define OFF_W1S   101376
#define OFF_CHK0  75264
#define OFF_CHK1  150528
#define OFF_IDX   225792
#define SMEM_MAIN 226304

#define HOFF_HS   0
#define HOFF_H1   99328
#define HOFF_H2   133120
#define SMEM_HEAD 149760

__device__ __align__(16) __half g_W1h[E_ * D_];
__device__ __align__(16) __half g_W2h[D_ * D_];
__device__ __align__(16) float  g_hbuf[(size_t)B_ * L_ * D_];
__device__ __align__(16) float  g_dG[B_ * L_];

__device__ __forceinline__ float geluf(float x) {
    return 0.5f * x * (1.0f + erff(x * 0.7071067811865476f));
}
__device__ __forceinline__ uint32_t smem_u32(const void* p) {
    uint32_t a;
    asm("{ .reg .u64 t; cvta.to.shared.u64 t, %1; cvt.u32.u64 %0, t; }" : "=r"(a) : "l"(p));
    return a;
}
__device__ __forceinline__ void cp_async16(uint32_t dst, const void* src) {
    asm volatile("cp.async.cg.shared.global [%0], [%1], 16;\n" :: "r"(dst), "l"(src) : "memory");
}
__device__ __forceinline__ void cp_commit() { asm volatile("cp.async.commit_group;\n" ::: "memory"); }
__device__ __forceinline__ void cp_wait0()  { asm volatile("cp.async.wait_group 0;\n" ::: "memory"); }

__device__ __forceinline__ void ldsm4(uint32_t* r, uint32_t addr) {
    asm volatile("ldmatrix.sync.aligned.m8n8.x4.shared.b16 {%0,%1,%2,%3}, [%4];"
        : "=r"(r[0]), "=r"(r[1]), "=r"(r[2]), "=r"(r[3]) : "r"(addr));
}
__device__ __forceinline__ void ldsm4t(uint32_t* r, uint32_t addr) {
    asm volatile("ldmatrix.sync.aligned.m8n8.x4.trans.shared.b16 {%0,%1,%2,%3}, [%4];"
        : "=r"(r[0]), "=r"(r[1]), "=r"(r[2]), "=r"(r[3]) : "r"(addr));
}
__device__ __forceinline__ void mma16816(float* c, const uint32_t* a, uint32_t b0, uint32_t b1) {
    asm volatile("mma.sync.aligned.m16n8k16.row.col.f32.f16.f16.f32 "
        "{%0,%1,%2,%3}, {%4,%5,%6,%7}, {%8,%9}, {%0,%1,%2,%3};"
        : "+f"(c[0]), "+f"(c[1]), "+f"(c[2]), "+f"(c[3])
        : "r"(a[0]), "r"(a[1]), "r"(a[2]), "r"(a[3]), "r"(b0), "r"(b1));
}

// ============================================================
__global__ void k_convert(const float* __restrict__ fw1, const float* __restrict__ fw2) {
    int stride = gridDim.x * blockDim.x;
    int i0 = blockIdx.x * blockDim.x + threadIdx.x;
    for (int q = i0; q < E_ * D_; q += stride) g_W1h[q] = __float2half_rn(fw1[q]);
    for (int q = i0; q < D_ * D_; q += stride) g_W2h[q] = __float2half_rn(fw2[q]);
}

// ============================================================
// fused main: raw mma.sync, register epilogues, direct-gather finish
// 24 warps: 2(m) x 12(n); warp tile m48 x n32 (3 m16 x 4 n8)
// ============================================================
__global__ void __launch_bounds__(NTHREADS, 1)
k_main(const float* __restrict__ h_V, const float* __restrict__ h_E,
       const float* __restrict__ fb1, const float* __restrict__ fb2,
       const int* __restrict__ E_idx)
{
    extern __shared__ __align__(16) unsigned char smem[];
    const uint32_t sbase = smem_u32(smem);
    __half* A1s = (__half*)(smem + OFF_A1S);
    int*    idxs = (int*)(smem + OFF_IDX);

    const int t = threadIdx.x;
    const int warp = t >> 5, lane = t & 31;
    const int tile = blockIdx.x;
    const int rowbase = tile * TILE_M;
    const int b = rowbase / (L_ * Kn_);

    if (t < TILE_M) idxs[t] = E_idx[rowbase + t];

    // ---- stage W1 (cp.async) ----
    for (int q = t; q < (E_ * D_) / 8; q += NTHREADS) {     // 6144 x 16B
        int r = q / 48, c8 = q - r * 48;
        cp_async16(sbase + OFF_W1S + (r * 392 + c8 * 8) * 2, g_W1h + r * 384 + c8 * 8);
    }
    cp_commit();
    // ---- stage X tile fp32 -> fp16, stride 136 halfs ----
    {
        const float4* Xg = reinterpret_cast<const float4*>(h_E + (size_t)rowbase * E_);
        __half* Xs = (__half*)(smem + OFF_XS);
        for (int q = t; q < (TILE_M * E_) / 4; q += NTHREADS) {
            int m = q >> 5, c4 = q & 31;
            float4 v = Xg[q];
            __half2* d = reinterpret_cast<__half2*>(Xs + m * 136 + c4 * 4);
            d[0] = __floats2half2_rn(v.x, v.y);
            d[1] = __floats2half2_rn(v.z, v.w);
        }
    }
    cp_wait0();
    __syncthreads();

    const int wm = warp / 12;           // 0..1
    const int wn = warp % 12;           // 0..11
    const int mrow0 = wm * 48;
    const int ncol0 = wn * 32;
    const int g = lane >> 2, l2 = (lane & 3) * 2;

    float acc[3][4][4];
    #pragma unroll
    for (int i = 0; i < 3; i++)
        #pragma unroll
        for (int j = 0; j < 4; j++)
            #pragma unroll
            for (int r = 0; r < 4; r++) acc[i][j][r] = 0.f;

    // ldmatrix lane-address components (shared by A and trans-B)
    const uint32_t lrow = (uint32_t)(lane & 15);
    const uint32_t lhi16 = ((uint32_t)(lane >> 4)) << 4;    // 16B for upper half

    // ---- GEMM1: Xs[96][128] @ W1s[128][384] ----
    {
        const uint32_t aBase = sbase + OFF_XS + (mrow0 + lrow) * 272 + lhi16;
        const uint32_t bBase = sbase + OFF_W1S + lrow * 784 + (uint32_t)ncol0 * 2 + lhi16;
        #pragma unroll
        for (int ks = 0; ks < 8; ks++) {
            uint32_t a[3][4];
            #pragma unroll
            for (int i = 0; i < 3; i++) ldsm4(a[i], aBase + i * 4352 + ks * 32);
            #pragma unroll
            for (int jp = 0; jp < 2; jp++) {
                uint32_t bf[4];
                ldsm4t(bf, bBase + jp * 32 + ks * 12544);
                #pragma unroll
                for (int i = 0; i < 3; i++) {
                    mma16816(acc[i][jp * 2],     a[i], bf[0], bf[1]);
                    mma16816(acc[i][jp * 2 + 1], a[i], bf[2], bf[3]);
                }
            }
        }
    }
    __syncthreads();                    // Xs/W1s dead; chunk region free

    // ---- kick off W2 chunk 0 load (overlaps epilogue) ----
    {
        const __half* src = g_W2h;      // rows 0..95
        for (int q = t; q < 96 * 48; q += NTHREADS) {
            int r = q / 48, c8 = q - r * 48;
            cp_async16(sbase + OFF_CHK0 + (r * 392 + c8 * 8) * 2, src + r * 384 + c8 * 8);
        }
        cp_commit();
    }

    // ---- GEMM1 epilogue in registers: +fb1, gelu, fp16 -> A1s ----
    #pragma unroll
    for (int i = 0; i < 3; i++) {
        int r0 = mrow0 + i * 16 + g;
        #pragma unroll
        for (int j = 0; j < 4; j++) {
            int col = ncol0 + j * 8 + l2;
            float bb0 = __ldg(fb1 + col), bb1 = __ldg(fb1 + col + 1);
            *reinterpret_cast<__half2*>(A1s + r0 * 392 + col) =
                __floats2half2_rn(geluf(acc[i][j][0] + bb0), geluf(acc[i][j][1] + bb1));
            *reinterpret_cast<__half2*>(A1s + (r0 + 8) * 392 + col) =
                __floats2half2_rn(geluf(acc[i][j][2] + bb0), geluf(acc[i][j][3] + bb1));
        }
    }
    #pragma unroll
    for (int i = 0; i < 3; i++)
        #pragma unroll
        for (int j = 0; j < 4; j++)
            #pragma unroll
            for (int r = 0; r < 4; r++) acc[i][j][r] = 0.f;
    cp_wait0();
    __syncthreads();                    // chunk0 ready, A1s complete

    // ---- GEMM2: A1s[96][384] @ W2[384][384], 4 chunks of k=96 ----
    {
        const uint32_t aBase = sbase + OFF_A1S + (mrow0 + lrow) * 784 + lhi16;
        const uint32_t bRow = lrow * 784 + (uint32_t)ncol0 * 2 + lhi16;
        for (int c = 0; c < 4; c++) {
            if (c < 3) {                // prefetch chunk c+1 into other buffer
                const __half* src = g_W2h + (size_t)(c + 1) * 96 * D_;
                uint32_t dst = sbase + (((c + 1) & 1) ? OFF_CHK1 : OFF_CHK0);
                for (int q = t; q < 96 * 48; q += NTHREADS) {
                    int r = q / 48, c8 = q - r * 48;
                    cp_async16(dst + (r * 392 + c8 * 8) * 2, src + r * 384 + c8 * 8);
                }
                cp_commit();
            }
            const uint32_t bBase = sbase + ((c & 1) ? OFF_CHK1 : OFF_CHK0) + bRow;
            const uint32_t aOff = aBase + c * 192;          // c*96 halfs = 192B
            #pragma unroll
            for (int ks = 0; ks < 6; ks++) {
                uint32_t a[3][4];
                #pragma unroll
                for (int i = 0; i < 3; i++) ldsm4(a[i], aOff + i * 12544 + ks * 32); // 16 rows x 784B
                #pragma unroll
                for (int jp = 0; jp < 2; jp++) {
                    uint32_t bf[4];
                    ldsm4t(bf, bBase + jp * 32 + ks * 12544);
                    #pragma unroll
                    for (int i = 0; i < 3; i++) {
                        mma16816(acc[i][jp * 2],     a[i], bf[0], bf[1]);
                        mma16816(acc[i][jp * 2 + 1], a[i], bf[2], bf[3]);
                    }
                }
            }
            if (c < 3) { cp_wait0(); __syncthreads(); }
        }
    }

    // ---- direct epilogue: +fb2, gelu, * gathered x_j, warp-reduce over rows ----
    // warp (wm, wn): rows wm*48 + i*16 + g (+8) -> group wm; cols ncol0 + j*8 + l2 (+1)
    {
        const float* hVb = h_V + (size_t)b * L_ * D_;
        int rIdx[3][2];
        #pragma unroll
        for (int i = 0; i < 3; i++) {
            rIdx[i][0] = idxs[mrow0 + i * 16 + g];
            rIdx[i][1] = idxs[mrow0 + i * 16 + g + 8];
        }
        float* outRow = g_hbuf + (size_t)(tile * 2 + wm) * D_;
        #pragma unroll
        for (int j = 0; j < 4; j++) {
            int col = ncol0 + j * 8 + l2;
            float bb0 = __ldg(fb2 + col), bb1 = __ldg(fb2 + col + 1);
            float p0 = 0.f, p1 = 0.f;
            #pragma unroll
            for (int i = 0; i < 3; i++) {
                float2 x0 = *reinterpret_cast<const float2*>(hVb + (size_t)rIdx[i][0] * D_ + col);
                float2 x1 = *reinterpret_cast<const float2*>(hVb + (size_t)rIdx[i][1] * D_ + col);
                p0 += geluf(acc[i][j][0] + bb0) * x0.x;
                p1 += geluf(acc[i][j][1] + bb1) * x0.y;
                p0 += geluf(acc[i][j][2] + bb0) * x1.x;
                p1 += geluf(acc[i][j][3] + bb1) * x1.y;
            }
            // reduce over g (lane bits 2..4)
            #pragma unroll
            for (int m = 4; m <= 16; m <<= 1) {
                p0 += __shfl_xor_sync(0xffffffff, p0, m);
                p1 += __shfl_xor_sync(0xffffffff, p1, m);
            }
            if (lane < 4)
                *reinterpret_cast<float2*>(outRow + col) = make_float2(p0, p1);
        }
    }
}

// ============================================================
__global__ void __launch_bounds__(256, 1)
k_head(const float* __restrict__ hw1, const float* __restrict__ hb1,
       const float* __restrict__ hw2, const float* __restrict__ hb2,
       const float* __restrict__ hw3, const float* __restrict__ hb3)
{
    extern __shared__ unsigned char sm[];
    float* hs  = (float*)(sm + HOFF_HS);
    float* h1s = (float*)(sm + HOFF_H1);
    float* h2s = (float*)(sm + HOFF_H2);
    const int t = threadIdx.x;
    const int row0 = blockIdx.x * 64;

    for (int e = t; e < 64 * D_; e += 256) {
        int r = e / D_, n = e - r * D_;
        hs[r * 388 + n] = g_hbuf[(size_t)(row0 + r) * D_ + n];
    }
    __syncthreads();
    {
        const int u = t & 127, rb = t >> 7;
        float accv[32];
        #pragma unroll
        for (int r = 0; r < 32; r++) accv[r] = 0.f;
        const float* hb = hs + (rb * 32) * 388;
        for (int d0 = 0; d0 < D_; d0 += 4) {
            float w0 = hw1[(d0 + 0) * H_ + u], w1 = hw1[(d0 + 1) * H_ + u];
            float w2 = hw1[(d0 + 2) * H_ + u], w3 = hw1[(d0 + 3) * H_ + u];
            #pragma unroll
            for (int r = 0; r < 32; r++) {
                float4 hv = *reinterpret_cast<const float4*>(hb + r * 388 + d0);
                accv[r] += hv.x * w0 + hv.y * w1 + hv.z * w2 + hv.w * w3;
            }
        }
        float b1 = hb1[u];
        #pragma unroll
        for (int r = 0; r < 32; r++) h1s[(rb * 32 + r) * 132 + u] = geluf(accv[r] + b1);
    }
    __syncthreads();
    {
        const int u = t & 63, rb = t >> 6;
        float accv[16];
        #pragma unroll
        for (int r = 0; r < 16; r++) accv[r] = 0.f;
        const float* hb = h1s + (rb * 16) * 132;
        for (int d0 = 0; d0 < H_; d0 += 4) {
            float w0 = hw2[(d0 + 0) * 64 + u], w1 = hw2[(d0 + 1) * 64 + u];
            float w2 = hw2[(d0 + 2) * 64 + u], w3 = hw2[(d0 + 3) * 64 + u];
            #pragma unroll
            for (int r = 0; r < 16; r++) {
                float4 hv = *reinterpret_cast<const float4*>(hb + r * 132 + d0);
                accv[r] += hv.x * w0 + hv.y * w1 + hv.z * w2 + hv.w * w3;
            }
        }
        float b2 = hb2[u];
        #pragma unroll
        for (int r = 0; r < 16; r++) h2s[(rb * 16 + r) * 65 + u] = geluf(accv[r] + b2);
    }
    __syncthreads();
    if (t < 64) {
        float s = hb3[0];
        #pragma unroll 8
        for (int j = 0; j < 64; j++) s += h2s[t * 65 + j] * hw3[j];
        g_dG[row0 + t] = s;
    }
}

// ============================================================
__global__ void k_final(const float* __restrict__ mask, float* __restrict__ out) {
    const int w = threadIdx.x >> 5, lane = threadIdx.x & 31;
    if (w < B_) {
        float s = 0.f, ms = 0.f;
        for (int l = lane; l < L_; l += 32) {
            float mk = mask[w * L_ + l];
            s  += g_dG[w * L_ + l] * mk;
            ms += mk;
        }
        #pragma unroll
        for (int o = 16; o; o >>= 1) {
            s  += __shfl_down_sync(0xffffffff, s, o);
            ms += __shfl_down_sync(0xffffffff, ms, o);
        }
        if (lane == 0) out[w] = s / sqrtf(fmaxf(ms, 1.0f));
    }
}

// ============================================================
extern "C" void kernel_launch(void* const* d_in, const int* in_sizes, int n_in,
                              void* d_out, int out_size)
{
    const float* h_V  = (const float*)d_in[0];
    const float* h_E  = (const float*)d_in[1];
    const float* mask = (const float*)d_in[2];
    const float* fw1  = (const float*)d_in[3];
    const float* fb1  = (const float*)d_in[4];
    const float* fw2  = (const float*)d_in[5];
    const float* fb2  = (const float*)d_in[6];
    const float* hw1  = (const float*)d_in[7];
    const float* hb1  = (const float*)d_in[8];
    const float* hw2  = (const float*)d_in[9];
    const float* hb2  = (const float*)d_in[10];
    const float* hw3  = (const float*)d_in[11];
    const float* hb3  = (const float*)d_in[12];
    const int*   E_idx = (const int*)d_in[13];
    float* out = (float*)d_out;

    cudaFuncSetAttribute(k_main, cudaFuncAttributeMaxDynamicSharedMemorySize, SMEM_MAIN);
    cudaFuncSetAttribute(k_head, cudaFuncAttributeMaxDynamicSharedMemorySize, SMEM_HEAD);

    k_convert<<<192, 256>>>(fw1, fw2);
    k_main<<<NTILES, NTHREADS, SMEM_MAIN>>>(h_V, h_E, fb1, fb2, E_idx);
    k_head<<<B_ * L_ / 64, 256, SMEM_HEAD>>>(hw1, hb1, hw2, hb2, hw3, hb3);
    k_final<<<1, 512>>>(mask, out);
}

// round 9
// speedup vs baseline: 2.2774x; 1.1762x over previous
#include <cuda_runtime.h>
#include <cuda_fp16.h>
#include <cstdint>

#define B_  16
#define L_  512
#define Kn_ 48
#define E_  128
#define D_  384
#define H_  128

#define TILE_M  96
#define NTILES  4096
#define NTHREADS 768

// ---- smem layout (bytes) ----
// A1s [96][392] half : [0, 75264)                      (GEMM1 out, GEMM2 in)
// Xs  [96][136] half : [75264, 101376)                 (dead after GEMM1 mainloop)
// W1s [128][392]half : [101376, 201728)                (dead after GEMM1 mainloop)
// chk0 [96][392]half : alias [75264, 150528)           (live during GEMM2)
// chk1 [96][392]half : alias [150528, 225792)
// idxs 96 int        : [225792, 226176)
#define OFF_A1S   0
#define OFF_XS    75264
#define OFF_W1S   101376
#define OFF_CHK0  75264
#define OFF_CHK1  150528
#define OFF_IDX   225792
#define SMEM_MAIN 226304

#define HOFF_HS   0
#define HOFF_H1   99328
#define HOFF_H2   133120
#define SMEM_HEAD 149760

__device__ __align__(16) __half g_W1h[E_ * D_];
__device__ __align__(16) __half g_W2h[D_ * D_];
__device__ __align__(16) float  g_hbuf[(size_t)B_ * L_ * D_];
__device__ __align__(16) float  g_dG[B_ * L_];

// exact erf-gelu (head kernel — negligible count, keep max accuracy)
__device__ __forceinline__ float geluf(float x) {
    return 0.5f * x * (1.0f + erff(x * 0.7071067811865476f));
}
// fast tanh-form gelu via HW MUFU.TANH (k_main bulk path)
__device__ __forceinline__ float gelu_fast(float x) {
    float x2 = x * x;
    float u = x * fmaf(0.044715f * 0.7978845608028654f, x2, 0.7978845608028654f);
    float t;
    asm("tanh.approx.f32 %0, %1;" : "=f"(t) : "f"(u));
    return 0.5f * x * (1.0f + t);
}
__device__ __forceinline__ uint32_t smem_u32(const void* p) {
    uint32_t a;
    asm("{ .reg .u64 t; cvta.to.shared.u64 t, %1; cvt.u32.u64 %0, t; }" : "=r"(a) : "l"(p));
    return a;
}
__device__ __forceinline__ void cp_async16(uint32_t dst, const void* src) {
    asm volatile("cp.async.cg.shared.global [%0], [%1], 16;\n" :: "r"(dst), "l"(src) : "memory");
}
__device__ __forceinline__ void cp_commit() { asm volatile("cp.async.commit_group;\n" ::: "memory"); }
__device__ __forceinline__ void cp_wait0()  { asm volatile("cp.async.wait_group 0;\n" ::: "memory"); }

__device__ __forceinline__ void ldsm4(uint32_t* r, uint32_t addr) {
    asm volatile("ldmatrix.sync.aligned.m8n8.x4.shared.b16 {%0,%1,%2,%3}, [%4];"
        : "=r"(r[0]), "=r"(r[1]), "=r"(r[2]), "=r"(r[3]) : "r"(addr));
}
__device__ __forceinline__ void ldsm4t(uint32_t* r, uint32_t addr) {
    asm volatile("ldmatrix.sync.aligned.m8n8.x4.trans.shared.b16 {%0,%1,%2,%3}, [%4];"
        : "=r"(r[0]), "=r"(r[1]), "=r"(r[2]), "=r"(r[3]) : "r"(addr));
}
__device__ __forceinline__ void mma16816(float* c, const uint32_t* a, uint32_t b0, uint32_t b1) {
    asm volatile("mma.sync.aligned.m16n8k16.row.col.f32.f16.f16.f32 "
        "{%0,%1,%2,%3}, {%4,%5,%6,%7}, {%8,%9}, {%0,%1,%2,%3};"
        : "+f"(c[0]), "+f"(c[1]), "+f"(c[2]), "+f"(c[3])
        : "r"(a[0]), "r"(a[1]), "r"(a[2]), "r"(a[3]), "r"(b0), "r"(b1));
}

// ============================================================
__global__ void k_convert(const float* __restrict__ fw1, const float* __restrict__ fw2) {
    int stride = gridDim.x * blockDim.x;
    int i0 = blockIdx.x * blockDim.x + threadIdx.x;
    for (int q = i0; q < E_ * D_; q += stride) g_W1h[q] = __float2half_rn(fw1[q]);
    for (int q = i0; q < D_ * D_; q += stride) g_W2h[q] = __float2half_rn(fw2[q]);
}

// ============================================================
// fused main: raw mma.sync, register epilogues, direct-gather finish
// 24 warps: 2(m) x 12(n); warp tile m48 x n32 (3 m16 x 4 n8)
// ============================================================
__global__ void __launch_bounds__(NTHREADS, 1)
k_main(const float* __restrict__ h_V, const float* __restrict__ h_E,
       const float* __restrict__ fb1, const float* __restrict__ fb2,
       const int* __restrict__ E_idx)
{
    extern __shared__ __align__(16) unsigned char smem[];
    const uint32_t sbase = smem_u32(smem);
    __half* A1s = (__half*)(smem + OFF_A1S);
    int*    idxs = (int*)(smem + OFF_IDX);

    const int t = threadIdx.x;
    const int warp = t >> 5, lane = t & 31;
    const int tile = blockIdx.x;
    const int rowbase = tile * TILE_M;
    const int b = rowbase / (L_ * Kn_);

    if (t < TILE_M) idxs[t] = E_idx[rowbase + t];

    // ---- stage W1 (cp.async) ----
    for (int q = t; q < (E_ * D_) / 8; q += NTHREADS) {     // 6144 x 16B
        int r = q / 48, c8 = q - r * 48;
        cp_async16(sbase + OFF_W1S + (r * 392 + c8 * 8) * 2, g_W1h + r * 384 + c8 * 8);
    }
    cp_commit();
    // ---- stage X tile fp32 -> fp16, stride 136 halfs ----
    {
        const float4* Xg = reinterpret_cast<const float4*>(h_E + (size_t)rowbase * E_);
        __half* Xs = (__half*)(smem + OFF_XS);
        for (int q = t; q < (TILE_M * E_) / 4; q += NTHREADS) {
            int m = q >> 5, c4 = q & 31;
            float4 v = Xg[q];
            __half2* d = reinterpret_cast<__half2*>(Xs + m * 136 + c4 * 4);
            d[0] = __floats2half2_rn(v.x, v.y);
            d[1] = __floats2half2_rn(v.z, v.w);
        }
    }
    cp_wait0();
    __syncthreads();

    const int wm = warp / 12;           // 0..1
    const int wn = warp % 12;           // 0..11
    const int mrow0 = wm * 48;
    const int ncol0 = wn * 32;
    const int g = lane >> 2, l2 = (lane & 3) * 2;

    float acc[3][4][4];
    #pragma unroll
    for (int i = 0; i < 3; i++)
        #pragma unroll
        for (int j = 0; j < 4; j++)
            #pragma unroll
            for (int r = 0; r < 4; r++) acc[i][j][r] = 0.f;

    const uint32_t lrow = (uint32_t)(lane & 15);
    const uint32_t lhi16 = ((uint32_t)(lane >> 4)) << 4;

    // ---- GEMM1: Xs[96][128] @ W1s[128][384] ----
    {
        const uint32_t aBase = sbase + OFF_XS + (mrow0 + lrow) * 272 + lhi16;
        const uint32_t bBase = sbase + OFF_W1S + lrow * 784 + (uint32_t)ncol0 * 2 + lhi16;
        #pragma unroll
        for (int ks = 0; ks < 8; ks++) {
            uint32_t a[3][4];
            #pragma unroll
            for (int i = 0; i < 3; i++) ldsm4(a[i], aBase + i * 4352 + ks * 32);
            #pragma unroll
            for (int jp = 0; jp < 2; jp++) {
                uint32_t bf[4];
                ldsm4t(bf, bBase + jp * 32 + ks * 12544);
                #pragma unroll
                for (int i = 0; i < 3; i++) {
                    mma16816(acc[i][jp * 2],     a[i], bf[0], bf[1]);
                    mma16816(acc[i][jp * 2 + 1], a[i], bf[2], bf[3]);
                }
            }
        }
    }
    __syncthreads();                    // Xs/W1s dead; chunk region free

    // ---- kick off W2 chunk 0 load (overlaps epilogue) ----
    {
        const __half* src = g_W2h;      // rows 0..95
        for (int q = t; q < 96 * 48; q += NTHREADS) {
            int r = q / 48, c8 = q - r * 48;
            cp_async16(sbase + OFF_CHK0 + (r * 392 + c8 * 8) * 2, src + r * 384 + c8 * 8);
        }
        cp_commit();
    }

    // ---- GEMM1 epilogue in registers: +fb1, gelu, fp16 -> A1s ----
    #pragma unroll
    for (int i = 0; i < 3; i++) {
        int r0 = mrow0 + i * 16 + g;
        #pragma unroll
        for (int j = 0; j < 4; j++) {
            int col = ncol0 + j * 8 + l2;
            float bb0 = __ldg(fb1 + col), bb1 = __ldg(fb1 + col + 1);
            *reinterpret_cast<__half2*>(A1s + r0 * 392 + col) =
                __floats2half2_rn(gelu_fast(acc[i][j][0] + bb0), gelu_fast(acc[i][j][1] + bb1));
            *reinterpret_cast<__half2*>(A1s + (r0 + 8) * 392 + col) =
                __floats2half2_rn(gelu_fast(acc[i][j][2] + bb0), gelu_fast(acc[i][j][3] + bb1));
        }
    }
    #pragma unroll
    for (int i = 0; i < 3; i++)
        #pragma unroll
        for (int j = 0; j < 4; j++)
            #pragma unroll
            for (int r = 0; r < 4; r++) acc[i][j][r] = 0.f;
    cp_wait0();
    __syncthreads();                    // chunk0 ready, A1s complete

    // ---- GEMM2: A1s[96][384] @ W2[384][384], 4 chunks of k=96 ----
    {
        const uint32_t aBase = sbase + OFF_A1S + (mrow0 + lrow) * 784 + lhi16;
        const uint32_t bRow = lrow * 784 + (uint32_t)ncol0 * 2 + lhi16;
        for (int c = 0; c < 4; c++) {
            if (c < 3) {                // prefetch chunk c+1 into other buffer
                const __half* src = g_W2h + (size_t)(c + 1) * 96 * D_;
                uint32_t dst = sbase + (((c + 1) & 1) ? OFF_CHK1 : OFF_CHK0);
                for (int q = t; q < 96 * 48; q += NTHREADS) {
                    int r = q / 48, c8 = q - r * 48;
                    cp_async16(dst + (r * 392 + c8 * 8) * 2, src + r * 384 + c8 * 8);
                }
                cp_commit();
            }
            const uint32_t bBase = sbase + ((c & 1) ? OFF_CHK1 : OFF_CHK0) + bRow;
            const uint32_t aOff = aBase + c * 192;          // c*96 halfs = 192B
            #pragma unroll
            for (int ks = 0; ks < 6; ks++) {
                uint32_t a[3][4];
                #pragma unroll
                for (int i = 0; i < 3; i++) ldsm4(a[i], aOff + i * 12544 + ks * 32); // 16 rows x 784B
                #pragma unroll
                for (int jp = 0; jp < 2; jp++) {
                    uint32_t bf[4];
                    ldsm4t(bf, bBase + jp * 32 + ks * 12544);
                    #pragma unroll
                    for (int i = 0; i < 3; i++) {
                        mma16816(acc[i][jp * 2],     a[i], bf[0], bf[1]);
                        mma16816(acc[i][jp * 2 + 1], a[i], bf[2], bf[3]);
                    }
                }
            }
            if (c < 3) { cp_wait0(); __syncthreads(); }
        }
    }

    // ---- direct epilogue: +fb2, gelu, * gathered x_j, warp-reduce over rows ----
    {
        const float* hVb = h_V + (size_t)b * L_ * D_;
        int rIdx[3][2];
        #pragma unroll
        for (int i = 0; i < 3; i++) {
            rIdx[i][0] = idxs[mrow0 + i * 16 + g];
            rIdx[i][1] = idxs[mrow0 + i * 16 + g + 8];
        }
        float* outRow = g_hbuf + (size_t)(tile * 2 + wm) * D_;
        #pragma unroll
        for (int j = 0; j < 4; j++) {
            int col = ncol0 + j * 8 + l2;
            float bb0 = __ldg(fb2 + col), bb1 = __ldg(fb2 + col + 1);
            float p0 = 0.f, p1 = 0.f;
            #pragma unroll
            for (int i = 0; i < 3; i++) {
                float2 x0 = *reinterpret_cast<const float2*>(hVb + (size_t)rIdx[i][0] * D_ + col);
                float2 x1 = *reinterpret_cast<const float2*>(hVb + (size_t)rIdx[i][1] * D_ + col);
                p0 += gelu_fast(acc[i][j][0] + bb0) * x0.x;
                p1 += gelu_fast(acc[i][j][1] + bb1) * x0.y;
                p0 += gelu_fast(acc[i][j][2] + bb0) * x1.x;
                p1 += gelu_fast(acc[i][j][3] + bb1) * x1.y;
            }
            #pragma unroll
            for (int m = 4; m <= 16; m <<= 1) {
                p0 += __shfl_xor_sync(0xffffffff, p0, m);
                p1 += __shfl_xor_sync(0xffffffff, p1, m);
            }
            if (lane < 4)
                *reinterpret_cast<float2*>(outRow + col) = make_float2(p0, p1);
        }
    }
}

// ============================================================
__global__ void __launch_bounds__(256, 1)
k_head(const float* __restrict__ hw1, const float* __restrict__ hb1,
       const float* __restrict__ hw2, const float* __restrict__ hb2,
       const float* __restrict__ hw3, const float* __restrict__ hb3)
{
    extern __shared__ unsigned char sm[];
    float* hs  = (float*)(sm + HOFF_HS);
    float* h1s = (float*)(sm + HOFF_H1);
    float* h2s = (float*)(sm + HOFF_H2);
    const int t = threadIdx.x;
    const int row0 = blockIdx.x * 64;

    for (int e = t; e < 64 * D_; e += 256) {
        int r = e / D_, n = e - r * D_;
        hs[r * 388 + n] = g_hbuf[(size_t)(row0 + r) * D_ + n];
    }
    __syncthreads();
    {
        const int u = t & 127, rb = t >> 7;
        float accv[32];
        #pragma unroll
        for (int r = 0; r < 32; r++) accv[r] = 0.f;
        const float* hb = hs + (rb * 32) * 388;
        for (int d0 = 0; d0 < D_; d0 += 4) {
            float w0 = hw1[(d0 + 0) * H_ + u], w1 = hw1[(d0 + 1) * H_ + u];
            float w2 = hw1[(d0 + 2) * H_ + u], w3 = hw1[(d0 + 3) * H_ + u];
            #pragma unroll
            for (int r = 0; r < 32; r++) {
                float4 hv = *reinterpret_cast<const float4*>(hb + r * 388 + d0);
                accv[r] += hv.x * w0 + hv.y * w1 + hv.z * w2 + hv.w * w3;
            }
        }
        float b1 = hb1[u];
        #pragma unroll
        for (int r = 0; r < 32; r++) h1s[(rb * 32 + r) * 132 + u] = geluf(accv[r] + b1);
    }
    __syncthreads();
    {
        const int u = t & 63, rb = t >> 6;
        float accv[16];
        #pragma unroll
        for (int r = 0; r < 16; r++) accv[r] = 0.f;
        const float* hb = h1s + (rb * 16) * 132;
        for (int d0 = 0; d0 < H_; d0 += 4) {
            float w0 = hw2[(d0 + 0) * 64 + u], w1 = hw2[(d0 + 1) * 64 + u];
            float w2 = hw2[(d0 + 2) * 64 + u], w3 = hw2[(d0 + 3) * 64 + u];
            #pragma unroll
            for (int r = 0; r < 16; r++) {
                float4 hv = *reinterpret_cast<const float4*>(hb + r * 132 + d0);
                accv[r] += hv.x * w0 + hv.y * w1 + hv.z * w2 + hv.w * w3;
            }
        }
        float b2 = hb2[u];
        #pragma unroll
        for (int r = 0; r < 16; r++) h2s[(rb * 16 + r) * 65 + u] = geluf(accv[r] + b2);
    }
    __syncthreads();
    if (t < 64) {
        float s = hb3[0];
        #pragma unroll 8
        for (int j = 0; j < 64; j++) s += h2s[t * 65 + j] * hw3[j];
        g_dG[row0 + t] = s;
    }
}

// ============================================================
__global__ void k_final(const float* __restrict__ mask, float* __restrict__ out) {
    const int w = threadIdx.x >> 5, lane = threadIdx.x & 31;
    if (w < B_) {
        float s = 0.f, ms = 0.f;
        for (int l = lane; l < L_; l += 32) {
            float mk = mask[w * L_ + l];
            s  += g_dG[w * L_ + l] * mk;
            ms += mk;
        }
        #pragma unroll
        for (int o = 16; o; o >>= 1) {
            s  += __shfl_down_sync(0xffffffff, s, o);
            ms += __shfl_down_sync(0xffffffff, ms, o);
        }
        if (lane == 0) out[w] = s / sqrtf(fmaxf(ms, 1.0f));
    }
}

// ============================================================
extern "C" void kernel_launch(void* const* d_in, const int* in_sizes, int n_in,
                              void* d_out, int out_size)
{
    const float* h_V  = (const float*)d_in[0];
    const float* h_E  = (const float*)d_in[1];
    const float* mask = (const float*)d_in[2];
    const float* fw1  = (const float*)d_in[3];
    const float* fb1  = (const float*)d_in[4];
    const float* fw2  = (const float*)d_in[5];
    const float* fb2  = (const float*)d_in[6];
    const float* hw1  = (const float*)d_in[7];
    const float* hb1  = (const float*)d_in[8];
    const float* hw2  = (const float*)d_in[9];
    const float* hb2  = (const float*)d_in[10];
    const float* hw3  = (const float*)d_in[11];
    const float* hb3  = (const float*)d_in[12];
    const int*   E_idx = (const int*)d_in[13];
    float* out = (float*)d_out;

    cudaFuncSetAttribute(k_main, cudaFuncAttributeMaxDynamicSharedMemorySize, SMEM_MAIN);
    cudaFuncSetAttribute(k_head, cudaFuncAttributeMaxDynamicSharedMemorySize, SMEM_HEAD);

    k_convert<<<192, 256>>>(fw1, fw2);
    k_main<<<NTILES, NTHREADS, SMEM_MAIN>>>(h_V, h_E, fb1, fb2, E_idx);
    k_head<<<B_ * L_ / 64, 256, SMEM_HEAD>>>(hw1, hb1, hw2, hb2, hw3, hb3);
    k_final<<<1, 512>>>(mask, out);
}